// round 6
// baseline (speedup 1.0000x reference)
#include <cuda_runtime.h>
#include <math.h>

#define B_      4
#define L_      4096
#define DIM_    1024
#define STATE_  16
#define NC_     128             // chunks per batch
#define CHUNK_  (L_ / NC_)      // 32
#define WARM_   192             // warm-up steps

typedef unsigned long long ull;

// ---------------- scratch (no allocations allowed) ----------------
__device__ float g_dt[B_ * L_];                 // dt[b][t]
__device__ float g_bx[B_ * L_ * STATE_];        // Bx[b][t][i]
__device__ float g_states[B_ * L_ * STATE_];    // normalized states s[b][t][i]

// packed f32x2 FMA on RESIDENT 64-bit regs: c += a * b (lanewise), ZERO movs
__device__ __forceinline__ void ffma2u(ull& c, ull a, ull b) {
    asm("fma.rn.f32x2 %0, %1, %2, %0;" : "+l"(c) : "l"(a), "l"(b));
}
__device__ __forceinline__ float2 u2f(ull u) {
    float2 f;
    asm("mov.b64 {%0, %1}, %2;" : "=f"(f.x), "=f"(f.y) : "l"(u));
    return f;
}

// =================================================================
// K1: per-row projections, TWO rows per warp (W_B stream shared).
//   Bx[i] = sum_d x[d]*W_B[i][d]; dt = clip(softplus(x.dt_w + dt_b))
// All inner products as packed FFMA2 with resident ull operands.
// =================================================================
__global__ void __launch_bounds__(256) k1_proj(const float* __restrict__ x,
                                               const float* __restrict__ W_B,
                                               const float* __restrict__ dt_w,
                                               const float* __restrict__ dt_b) {
    int warp = (blockIdx.x * blockDim.x + threadIdx.x) >> 5;
    int lane = threadIdx.x & 31;
    int r0 = warp * 2;
    if (r0 >= B_ * L_) return;

    const ulonglong2* xr0 = reinterpret_cast<const ulonglong2*>(x + (size_t)r0 * DIM_) + lane;
    const ulonglong2* xr1 = reinterpret_cast<const ulonglong2*>(x + (size_t)(r0 + 1) * DIM_) + lane;
    ulonglong2 xv0[8], xv1[8];
    #pragma unroll
    for (int k = 0; k < 8; k++) { xv0[k] = xr0[k * 32]; xv1[k] = xr1[k * 32]; }

    float acc0[17], acc1[17];
    #pragma unroll
    for (int i = 0; i < 17; i++) {
        const float* wrow = (i < 16) ? (W_B + (size_t)i * DIM_) : dt_w;
        const ulonglong2* wr = reinterpret_cast<const ulonglong2*>(wrow) + lane;
        ull a0 = 0ull, a1 = 0ull, b0 = 0ull, b1 = 0ull;
        #pragma unroll
        for (int k = 0; k < 8; k++) {
            ulonglong2 w2 = wr[k * 32];
            ffma2u(a0, xv0[k].x, w2.x);
            ffma2u(a1, xv0[k].y, w2.y);
            ffma2u(b0, xv1[k].x, w2.x);
            ffma2u(b1, xv1[k].y, w2.y);
        }
        float2 fa0 = u2f(a0), fa1 = u2f(a1), fb0 = u2f(b0), fb1 = u2f(b1);
        acc0[i] = (fa0.x + fa0.y) + (fa1.x + fa1.y);
        acc1[i] = (fb0.x + fb0.y) + (fb1.x + fb1.y);
    }

    #pragma unroll
    for (int m = 16; m >= 1; m >>= 1) {
        #pragma unroll
        for (int i = 0; i < 17; i++) {
            acc0[i] += __shfl_xor_sync(0xffffffffu, acc0[i], m);
            acc1[i] += __shfl_xor_sync(0xffffffffu, acc1[i], m);
        }
    }

    if (lane == 0) {
        float dtb = dt_b[0];
        float4* bo0 = reinterpret_cast<float4*>(g_bx + (size_t)r0 * STATE_);
        bo0[0] = make_float4(acc0[0],  acc0[1],  acc0[2],  acc0[3]);
        bo0[1] = make_float4(acc0[4],  acc0[5],  acc0[6],  acc0[7]);
        bo0[2] = make_float4(acc0[8],  acc0[9],  acc0[10], acc0[11]);
        bo0[3] = make_float4(acc0[12], acc0[13], acc0[14], acc0[15]);
        float z0  = acc0[16] + dtb;
        float sp0 = (z0 > 15.f) ? z0 : log1pf(expf(z0));
        g_dt[r0] = fminf(fmaxf(sp0, 0.001f), 0.1f);

        float4* bo1 = reinterpret_cast<float4*>(g_bx + (size_t)(r0 + 1) * STATE_);
        bo1[0] = make_float4(acc1[0],  acc1[1],  acc1[2],  acc1[3]);
        bo1[1] = make_float4(acc1[4],  acc1[5],  acc1[6],  acc1[7]);
        bo1[2] = make_float4(acc1[8],  acc1[9],  acc1[10], acc1[11]);
        bo1[3] = make_float4(acc1[12], acc1[13], acc1[14], acc1[15]);
        float z1  = acc1[16] + dtb;
        float sp1 = (z1 > 15.f) ? z1 : log1pf(expf(z1));
        g_dt[r0 + 1] = fminf(fmaxf(sp1, 0.001f), 0.1f);
    }
}

// =================================================================
// K2: chunked sequential scan with warm-up, K0 fused in.
// Each block computes the spectral-scale fast path itself:
// sigma_max <= ||A||_F, so ||A||_F <= 0.99 -> scale == 1 exactly.
// (Power-iteration fallback per block for the rare case.)
// =================================================================
__global__ void __launch_bounds__(32) k2_scan(const float* __restrict__ A,
                                              const float* __restrict__ state_in,
                                              const float* __restrict__ ln_w,
                                              const float* __restrict__ ln_b) {
    const unsigned FULL = 0xffffffffu;
    __shared__ float sA[256];
    __shared__ float s_scale;

    int lane = threadIdx.x;
    int seg  = lane >> 4;
    int i    = lane & 15;
    int gidx = blockIdx.x * 2 + seg;  // 0..511
    int b     = gidx & 3;
    int chunk = gidx >> 2;            // same across the warp's two segs
    int cs   = chunk * CHUNK_;
    int ws   = cs - WARM_; if (ws < 0) ws = 0;
    int tend = cs + CHUNK_;

    // ---- fused spectral scale ----
    float ss = 0.f;
    #pragma unroll
    for (int j = 0; j < 8; j++) {
        float a = A[lane * 8 + j];
        sA[lane * 8 + j] = a;
        ss = fmaf(a, a, ss);
    }
    #pragma unroll
    for (int m = 16; m >= 1; m >>= 1) ss += __shfl_xor_sync(FULL, ss, m);
    float scale = 1.0f;
    if (ss > 0.9801f) {               // uniform branch; rarely taken
        __syncwarp();
        if (lane == 0) {
            float v[16];
            #pragma unroll
            for (int k = 0; k < 16; k++) v[k] = 1.0f;
            for (int it = 0; it < 400; ++it) {
                float u[16];
                for (int r = 0; r < 16; r++) {
                    float acc = 0.f;
                    for (int c = 0; c < 16; c++) acc = fmaf(sA[r * 16 + c], v[c], acc);
                    u[r] = acc;
                }
                float w2[16]; float nn = 0.f;
                for (int c = 0; c < 16; c++) {
                    float acc = 0.f;
                    for (int r = 0; r < 16; r++) acc = fmaf(sA[r * 16 + c], u[r], acc);
                    w2[c] = acc; nn += acc * acc;
                }
                float inv = rsqrtf(fmaxf(nn, 1e-30f));
                for (int c = 0; c < 16; c++) v[c] = w2[c] * inv;
            }
            float sig2 = 0.f;
            for (int r = 0; r < 16; r++) {
                float acc = 0.f;
                for (int c = 0; c < 16; c++) acc = fmaf(sA[r * 16 + c], v[c], acc);
                sig2 += acc * acc;
            }
            float sigma = sqrtf(sig2);
            s_scale = (sigma > 0.99f) ? (0.99f / sigma) : 1.0f;
        }
        __syncwarp();
        scale = s_scale;
    }

    // ---- per-lane constants ----
    float w_[16], b_[16];
    #pragma unroll
    for (int j = 0; j < 16; j += 4) {
        float4 t4 = *reinterpret_cast<const float4*>(ln_w + j);
        w_[j] = t4.x; w_[j + 1] = t4.y; w_[j + 2] = t4.z; w_[j + 3] = t4.w;
        float4 u4 = *reinterpret_cast<const float4*>(ln_b + j);
        b_[j] = u4.x; b_[j + 1] = u4.y; b_[j + 2] = u4.z; b_[j + 3] = u4.w;
    }
    float an[16], ap[16];
    #pragma unroll
    for (int j = 0; j < 16; j += 4) {
        float4 a4 = *reinterpret_cast<const float4*>(A + i * 16 + j);
        an[j] = a4.x * scale; an[j + 1] = a4.y * scale;
        an[j + 2] = a4.z * scale; an[j + 3] = a4.w * scale;
    }
    float aw1 = 0.f, ab = 0.f;
    #pragma unroll
    for (int j = 0; j < 16; j++) {
        ap[j] = an[j] * w_[j];
        aw1  += ap[j];
        ab    = fmaf(an[j], b_[j], ab);
    }
    float wi = ln_w[i];
    float bi = ln_b[i];

    const float* dtp = g_dt + (size_t)b * L_;
    const float* bxp = g_bx + (size_t)b * L_ * STATE_ + i;
    float*       stp = g_states + (size_t)b * L_ * STATE_ + i;

    // prologue: h_ws = s0 + dt[ws]*(An s0) + bx[ws]
    float s0 = (ws == 0) ? state_in[b * STATE_ + i] : 0.f;
    float p0 = 0.f, p1 = 0.f, p2 = 0.f, p3 = 0.f;
    #pragma unroll
    for (int j = 0; j < 16; j += 4) {
        p0 = fmaf(an[j],     __shfl_sync(FULL, s0, j,     16), p0);
        p1 = fmaf(an[j + 1], __shfl_sync(FULL, s0, j + 1, 16), p1);
        p2 = fmaf(an[j + 2], __shfl_sync(FULL, s0, j + 2, 16), p2);
        p3 = fmaf(an[j + 3], __shfl_sync(FULL, s0, j + 3, 16), p3);
    }
    float g0 = (p0 + p1) + (p2 + p3);
    float h = fmaf(dtp[ws], g0, s0) + bxp[(size_t)ws * STATE_];

    int tp1 = ws + 1; if (tp1 > L_ - 1) tp1 = L_ - 1;
    int tp2 = ws + 2; if (tp2 > L_ - 1) tp2 = L_ - 1;
    int tp3 = ws + 3; if (tp3 > L_ - 1) tp3 = L_ - 1;
    float dtA = dtp[tp1], bxA = bxp[(size_t)tp1 * STATE_];
    float dtB = dtp[tp2], bxB = bxp[(size_t)tp2 * STATE_];
    float dtC = dtp[tp3], bxC = bxp[(size_t)tp3 * STATE_];

    for (int t = ws; t < tend; ++t) {
        float hv[16];
        #pragma unroll
        for (int j = 0; j < 16; j++) hv[j] = __shfl_sync(FULL, h, j, 16);

        float m0, m1, m2, m3, u0, u1, q0, q1, q2, q3;
        m0 = ap[0] * hv[0]; m1 = ap[1] * hv[1]; m2 = ap[2] * hv[2]; m3 = ap[3] * hv[3];
        u0 = hv[0] + hv[1]; u1 = hv[2] + hv[3];
        q0 = hv[0] * hv[0]; q1 = hv[1] * hv[1]; q2 = hv[2] * hv[2]; q3 = hv[3] * hv[3];
        #pragma unroll
        for (int j = 4; j < 16; j += 4) {
            m0 = fmaf(ap[j],     hv[j],     m0);
            m1 = fmaf(ap[j + 1], hv[j + 1], m1);
            m2 = fmaf(ap[j + 2], hv[j + 2], m2);
            m3 = fmaf(ap[j + 3], hv[j + 3], m3);
            u0 += hv[j] + hv[j + 1];
            u1 += hv[j + 2] + hv[j + 3];
            q0 = fmaf(hv[j],     hv[j],     q0);
            q1 = fmaf(hv[j + 1], hv[j + 1], q1);
            q2 = fmaf(hv[j + 2], hv[j + 2], q2);
            q3 = fmaf(hv[j + 3], hv[j + 3], q3);
        }
        float g = (m0 + m1) + (m2 + m3);
        float u = u0 + u1;
        float q = (q0 + q1) + (q2 + q3);

        float mu    = u * 0.0625f;
        float var   = fmaf(-mu, mu, q * 0.0625f);
        float alpha = rsqrtf(var + 1e-5f);
        float hm    = h - mu;

        if (t >= cs) stp[(size_t)t * STATE_] = fmaf(alpha * hm, wi, bi);

        float dtn = dtA, bxn = bxA;
        dtA = dtB; bxA = bxB;
        dtB = dtC; bxB = bxC;
        int tn = t + 4; if (tn > L_ - 1) tn = L_ - 1;
        dtC = dtp[tn]; bxC = bxp[(size_t)tn * STATE_];

        float t1 = fmaf(-mu, aw1, g);
        float t2 = fmaf(dtn, t1, hm * wi);
        h = fmaf(alpha, t2, fmaf(dtn, ab, bi) + bxn);
    }
}

// =================================================================
// K3: y = states @ W_C^T + D*x.  Occupancy-first tiling:
//   one output column d per thread (W_C[d][:] = 8 resident ull regs),
//   64 rows per block staged through 4KB smem (broadcast LDS.64),
//   x loads scalar-coalesced with MLP=4, 1024 blocks, ~50 regs.
// =================================================================
#define K3R 64

__global__ void __launch_bounds__(256) k3_out(const float* __restrict__ x,
                                              const float* __restrict__ W_C,
                                              const float* __restrict__ D,
                                              float* __restrict__ out,
                                              int write_tail) {
    __shared__ float4 sstate[K3R * 4];   // 64 rows x 16 floats

    int rb = (blockIdx.x >> 2) * K3R;
    int d  = ((blockIdx.x & 3) << 8) + threadIdx.x;

    // cooperative state stage: 1024 floats = 256 float4, one per thread
    sstate[threadIdx.x] =
        reinterpret_cast<const float4*>(g_states + (size_t)rb * STATE_)[threadIdx.x];

    // W_C column-row d: 16 floats as 8 packed ull
    ull wv[8];
    {
        const ulonglong2* wp = reinterpret_cast<const ulonglong2*>(W_C + (size_t)d * STATE_);
        ulonglong2 t0 = wp[0], t1 = wp[1], t2 = wp[2], t3 = wp[3];
        wv[0] = t0.x; wv[1] = t0.y; wv[2] = t1.x; wv[3] = t1.y;
        wv[4] = t2.x; wv[5] = t2.y; wv[6] = t3.x; wv[7] = t3.y;
    }
    float dD = D[d];
    __syncthreads();

    const ull* sbase = reinterpret_cast<const ull*>(sstate);

    // x pipeline: 4 rows in flight
    float xb[4];
    #pragma unroll
    for (int j = 0; j < 4; j++)
        xb[j] = x[(size_t)(rb + j) * DIM_ + d];

    for (int r0 = 0; r0 < K3R; r0 += 4) {
        float xc[4];
        #pragma unroll
        for (int j = 0; j < 4; j++) xc[j] = xb[j];
        if (r0 + 4 < K3R) {
            #pragma unroll
            for (int j = 0; j < 4; j++)
                xb[j] = x[(size_t)(rb + r0 + 4 + j) * DIM_ + d];
        }

        #pragma unroll
        for (int j = 0; j < 4; j++) {
            const ull* sp = sbase + (size_t)(r0 + j) * 8;   // broadcast reads
            ull acc = 0ull;
            #pragma unroll
            for (int k = 0; k < 8; k++) ffma2u(acc, wv[k], sp[k]);
            float2 f = u2f(acc);
            out[(size_t)(rb + r0 + j) * DIM_ + d] = fmaf(dD, xc[j], f.x + f.y);
        }
    }

    // new_state = states[:, L-1, :]
    if (write_tail && blockIdx.x == 0 && threadIdx.x < B_ * STATE_) {
        int bb = threadIdx.x >> 4, ii = threadIdx.x & 15;
        out[(size_t)B_ * L_ * DIM_ + threadIdx.x] =
            g_states[((size_t)bb * L_ + (L_ - 1)) * STATE_ + ii];
    }
}

// =================================================================
extern "C" void kernel_launch(void* const* d_in, const int* in_sizes, int n_in,
                              void* d_out, int out_size) {
    const float* x     = (const float*)d_in[0];
    const float* state = (const float*)d_in[1];
    const float* A     = (const float*)d_in[2];
    const float* W_B   = (const float*)d_in[3];
    const float* W_C   = (const float*)d_in[4];
    const float* D     = (const float*)d_in[5];
    const float* dt_w  = (const float*)d_in[6];
    const float* dt_b  = (const float*)d_in[7];
    const float* ln_w  = (const float*)d_in[8];
    const float* ln_b  = (const float*)d_in[9];
    float* out = (float*)d_out;

    k1_proj<<<(B_ * L_ / 2 * 32) / 256, 256>>>(x, W_B, dt_w, dt_b);      // 1024 blocks
    k2_scan<<<(B_ * NC_) / 2, 32>>>(A, state, ln_w, ln_b);               // 256 blocks
    int tail = (out_size >= B_ * L_ * DIM_ + B_ * STATE_) ? 1 : 0;
    k3_out<<<(B_ * L_ / K3R) * 4, 256>>>(x, W_C, D, out, tail);          // 1024 blocks
}

// round 7
// speedup vs baseline: 1.0028x; 1.0028x over previous
#include <cuda_runtime.h>
#include <math.h>

#define B_      4
#define L_      4096
#define DIM_    1024
#define STATE_  16
#define NC_     128             // chunks per batch
#define CHUNK_  (L_ / NC_)      // 32
#define WARM_   192             // warm-up steps

typedef unsigned long long ull;

// ---------------- scratch (no allocations allowed) ----------------
__device__ float g_dt[B_ * L_];                 // dt[b][t]
__device__ float g_bx[B_ * L_ * STATE_];        // Bx[b][t][i]
__device__ float g_states[B_ * L_ * STATE_];    // normalized states s[b][t][i]

// packed f32x2 FMA on RESIDENT 64-bit regs: c += a * b (lanewise), ZERO movs
__device__ __forceinline__ void ffma2u(ull& c, ull a, ull b) {
    asm("fma.rn.f32x2 %0, %1, %2, %0;" : "+l"(c) : "l"(a), "l"(b));
}
__device__ __forceinline__ float2 u2f(ull u) {
    float2 f;
    asm("mov.b64 {%0, %1}, %2;" : "=f"(f.x), "=f"(f.y) : "l"(u));
    return f;
}

// =================================================================
// K1: per-row projections, TWO rows per warp (W_B stream shared).
//   Bx[i] = sum_d x[d]*W_B[i][d]; dt = clip(softplus(x.dt_w + dt_b))
// All inner products as packed FFMA2 with resident ull operands.
// =================================================================
__global__ void __launch_bounds__(256) k1_proj(const float* __restrict__ x,
                                               const float* __restrict__ W_B,
                                               const float* __restrict__ dt_w,
                                               const float* __restrict__ dt_b) {
    int warp = (blockIdx.x * blockDim.x + threadIdx.x) >> 5;
    int lane = threadIdx.x & 31;
    int r0 = warp * 2;
    if (r0 >= B_ * L_) return;

    const ulonglong2* xr0 = reinterpret_cast<const ulonglong2*>(x + (size_t)r0 * DIM_) + lane;
    const ulonglong2* xr1 = reinterpret_cast<const ulonglong2*>(x + (size_t)(r0 + 1) * DIM_) + lane;
    ulonglong2 xv0[8], xv1[8];
    #pragma unroll
    for (int k = 0; k < 8; k++) { xv0[k] = xr0[k * 32]; xv1[k] = xr1[k * 32]; }

    float acc0[17], acc1[17];
    #pragma unroll
    for (int i = 0; i < 17; i++) {
        const float* wrow = (i < 16) ? (W_B + (size_t)i * DIM_) : dt_w;
        const ulonglong2* wr = reinterpret_cast<const ulonglong2*>(wrow) + lane;
        ull a0 = 0ull, a1 = 0ull, b0 = 0ull, b1 = 0ull;
        #pragma unroll
        for (int k = 0; k < 8; k++) {
            ulonglong2 w2 = wr[k * 32];
            ffma2u(a0, xv0[k].x, w2.x);
            ffma2u(a1, xv0[k].y, w2.y);
            ffma2u(b0, xv1[k].x, w2.x);
            ffma2u(b1, xv1[k].y, w2.y);
        }
        float2 fa0 = u2f(a0), fa1 = u2f(a1), fb0 = u2f(b0), fb1 = u2f(b1);
        acc0[i] = (fa0.x + fa0.y) + (fa1.x + fa1.y);
        acc1[i] = (fb0.x + fb0.y) + (fb1.x + fb1.y);
    }

    #pragma unroll
    for (int m = 16; m >= 1; m >>= 1) {
        #pragma unroll
        for (int i = 0; i < 17; i++) {
            acc0[i] += __shfl_xor_sync(0xffffffffu, acc0[i], m);
            acc1[i] += __shfl_xor_sync(0xffffffffu, acc1[i], m);
        }
    }

    if (lane == 0) {
        float dtb = dt_b[0];
        float4* bo0 = reinterpret_cast<float4*>(g_bx + (size_t)r0 * STATE_);
        bo0[0] = make_float4(acc0[0],  acc0[1],  acc0[2],  acc0[3]);
        bo0[1] = make_float4(acc0[4],  acc0[5],  acc0[6],  acc0[7]);
        bo0[2] = make_float4(acc0[8],  acc0[9],  acc0[10], acc0[11]);
        bo0[3] = make_float4(acc0[12], acc0[13], acc0[14], acc0[15]);
        float z0  = acc0[16] + dtb;
        float sp0 = (z0 > 15.f) ? z0 : log1pf(expf(z0));
        g_dt[r0] = fminf(fmaxf(sp0, 0.001f), 0.1f);

        float4* bo1 = reinterpret_cast<float4*>(g_bx + (size_t)(r0 + 1) * STATE_);
        bo1[0] = make_float4(acc1[0],  acc1[1],  acc1[2],  acc1[3]);
        bo1[1] = make_float4(acc1[4],  acc1[5],  acc1[6],  acc1[7]);
        bo1[2] = make_float4(acc1[8],  acc1[9],  acc1[10], acc1[11]);
        bo1[3] = make_float4(acc1[12], acc1[13], acc1[14], acc1[15]);
        float z1  = acc1[16] + dtb;
        float sp1 = (z1 > 15.f) ? z1 : log1pf(expf(z1));
        g_dt[r0 + 1] = fminf(fmaxf(sp1, 0.001f), 0.1f);
    }
}

// =================================================================
// K2: chunked sequential scan with warm-up, K0 fused in.
// Each block computes the spectral-scale fast path itself:
// sigma_max <= ||A||_F, so ||A||_F <= 0.99 -> scale == 1 exactly.
// (Power-iteration fallback per block for the rare case.)
// =================================================================
__global__ void __launch_bounds__(32) k2_scan(const float* __restrict__ A,
                                              const float* __restrict__ state_in,
                                              const float* __restrict__ ln_w,
                                              const float* __restrict__ ln_b) {
    const unsigned FULL = 0xffffffffu;
    __shared__ float sA[256];
    __shared__ float s_scale;

    int lane = threadIdx.x;
    int seg  = lane >> 4;
    int i    = lane & 15;
    int gidx = blockIdx.x * 2 + seg;  // 0..511
    int b     = gidx & 3;
    int chunk = gidx >> 2;            // same across the warp's two segs
    int cs   = chunk * CHUNK_;
    int ws   = cs - WARM_; if (ws < 0) ws = 0;
    int tend = cs + CHUNK_;

    // ---- fused spectral scale ----
    float ss = 0.f;
    #pragma unroll
    for (int j = 0; j < 8; j++) {
        float a = A[lane * 8 + j];
        sA[lane * 8 + j] = a;
        ss = fmaf(a, a, ss);
    }
    #pragma unroll
    for (int m = 16; m >= 1; m >>= 1) ss += __shfl_xor_sync(FULL, ss, m);
    float scale = 1.0f;
    if (ss > 0.9801f) {               // uniform branch; rarely taken
        __syncwarp();
        if (lane == 0) {
            float v[16];
            #pragma unroll
            for (int k = 0; k < 16; k++) v[k] = 1.0f;
            for (int it = 0; it < 400; ++it) {
                float u[16];
                for (int r = 0; r < 16; r++) {
                    float acc = 0.f;
                    for (int c = 0; c < 16; c++) acc = fmaf(sA[r * 16 + c], v[c], acc);
                    u[r] = acc;
                }
                float w2[16]; float nn = 0.f;
                for (int c = 0; c < 16; c++) {
                    float acc = 0.f;
                    for (int r = 0; r < 16; r++) acc = fmaf(sA[r * 16 + c], u[r], acc);
                    w2[c] = acc; nn += acc * acc;
                }
                float inv = rsqrtf(fmaxf(nn, 1e-30f));
                for (int c = 0; c < 16; c++) v[c] = w2[c] * inv;
            }
            float sig2 = 0.f;
            for (int r = 0; r < 16; r++) {
                float acc = 0.f;
                for (int c = 0; c < 16; c++) acc = fmaf(sA[r * 16 + c], v[c], acc);
                sig2 += acc * acc;
            }
            float sigma = sqrtf(sig2);
            s_scale = (sigma > 0.99f) ? (0.99f / sigma) : 1.0f;
        }
        __syncwarp();
        scale = s_scale;
    }

    // ---- per-lane constants ----
    float w_[16], b_[16];
    #pragma unroll
    for (int j = 0; j < 16; j += 4) {
        float4 t4 = *reinterpret_cast<const float4*>(ln_w + j);
        w_[j] = t4.x; w_[j + 1] = t4.y; w_[j + 2] = t4.z; w_[j + 3] = t4.w;
        float4 u4 = *reinterpret_cast<const float4*>(ln_b + j);
        b_[j] = u4.x; b_[j + 1] = u4.y; b_[j + 2] = u4.z; b_[j + 3] = u4.w;
    }
    float an[16], ap[16];
    #pragma unroll
    for (int j = 0; j < 16; j += 4) {
        float4 a4 = *reinterpret_cast<const float4*>(A + i * 16 + j);
        an[j] = a4.x * scale; an[j + 1] = a4.y * scale;
        an[j + 2] = a4.z * scale; an[j + 3] = a4.w * scale;
    }
    float aw1 = 0.f, ab = 0.f;
    #pragma unroll
    for (int j = 0; j < 16; j++) {
        ap[j] = an[j] * w_[j];
        aw1  += ap[j];
        ab    = fmaf(an[j], b_[j], ab);
    }
    float wi = ln_w[i];
    float bi = ln_b[i];

    const float* dtp = g_dt + (size_t)b * L_;
    const float* bxp = g_bx + (size_t)b * L_ * STATE_ + i;
    float*       stp = g_states + (size_t)b * L_ * STATE_ + i;

    // prologue: h_ws = s0 + dt[ws]*(An s0) + bx[ws]
    float s0 = (ws == 0) ? state_in[b * STATE_ + i] : 0.f;
    float p0 = 0.f, p1 = 0.f, p2 = 0.f, p3 = 0.f;
    #pragma unroll
    for (int j = 0; j < 16; j += 4) {
        p0 = fmaf(an[j],     __shfl_sync(FULL, s0, j,     16), p0);
        p1 = fmaf(an[j + 1], __shfl_sync(FULL, s0, j + 1, 16), p1);
        p2 = fmaf(an[j + 2], __shfl_sync(FULL, s0, j + 2, 16), p2);
        p3 = fmaf(an[j + 3], __shfl_sync(FULL, s0, j + 3, 16), p3);
    }
    float g0 = (p0 + p1) + (p2 + p3);
    float h = fmaf(dtp[ws], g0, s0) + bxp[(size_t)ws * STATE_];

    int tp1 = ws + 1; if (tp1 > L_ - 1) tp1 = L_ - 1;
    int tp2 = ws + 2; if (tp2 > L_ - 1) tp2 = L_ - 1;
    int tp3 = ws + 3; if (tp3 > L_ - 1) tp3 = L_ - 1;
    float dtA = dtp[tp1], bxA = bxp[(size_t)tp1 * STATE_];
    float dtB = dtp[tp2], bxB = bxp[(size_t)tp2 * STATE_];
    float dtC = dtp[tp3], bxC = bxp[(size_t)tp3 * STATE_];

    for (int t = ws; t < tend; ++t) {
        float hv[16];
        #pragma unroll
        for (int j = 0; j < 16; j++) hv[j] = __shfl_sync(FULL, h, j, 16);

        float m0, m1, m2, m3, u0, u1, q0, q1, q2, q3;
        m0 = ap[0] * hv[0]; m1 = ap[1] * hv[1]; m2 = ap[2] * hv[2]; m3 = ap[3] * hv[3];
        u0 = hv[0] + hv[1]; u1 = hv[2] + hv[3];
        q0 = hv[0] * hv[0]; q1 = hv[1] * hv[1]; q2 = hv[2] * hv[2]; q3 = hv[3] * hv[3];
        #pragma unroll
        for (int j = 4; j < 16; j += 4) {
            m0 = fmaf(ap[j],     hv[j],     m0);
            m1 = fmaf(ap[j + 1], hv[j + 1], m1);
            m2 = fmaf(ap[j + 2], hv[j + 2], m2);
            m3 = fmaf(ap[j + 3], hv[j + 3], m3);
            u0 += hv[j] + hv[j + 1];
            u1 += hv[j + 2] + hv[j + 3];
            q0 = fmaf(hv[j],     hv[j],     q0);
            q1 = fmaf(hv[j + 1], hv[j + 1], q1);
            q2 = fmaf(hv[j + 2], hv[j + 2], q2);
            q3 = fmaf(hv[j + 3], hv[j + 3], q3);
        }
        float g = (m0 + m1) + (m2 + m3);
        float u = u0 + u1;
        float q = (q0 + q1) + (q2 + q3);

        float mu    = u * 0.0625f;
        float var   = fmaf(-mu, mu, q * 0.0625f);
        float alpha = rsqrtf(var + 1e-5f);
        float hm    = h - mu;

        if (t >= cs) stp[(size_t)t * STATE_] = fmaf(alpha * hm, wi, bi);

        float dtn = dtA, bxn = bxA;
        dtA = dtB; bxA = bxB;
        dtB = dtC; bxB = bxC;
        int tn = t + 4; if (tn > L_ - 1) tn = L_ - 1;
        dtC = dtp[tn]; bxC = bxp[(size_t)tn * STATE_];

        float t1 = fmaf(-mu, aw1, g);
        float t2 = fmaf(dtn, t1, hm * wi);
        h = fmaf(alpha, t2, fmaf(dtn, ab, bi) + bxn);
    }
}

// =================================================================
// K3: y = states @ W_C^T + D*x.  Occupancy-first tiling:
//   one output column d per thread (W_C[d][:] = 8 resident ull regs),
//   64 rows per block staged through 4KB smem (broadcast LDS.64),
//   x loads scalar-coalesced with MLP=4, 1024 blocks, ~50 regs.
// =================================================================
#define K3R 64

__global__ void __launch_bounds__(256) k3_out(const float* __restrict__ x,
                                              const float* __restrict__ W_C,
                                              const float* __restrict__ D,
                                              float* __restrict__ out,
                                              int write_tail) {
    __shared__ float4 sstate[K3R * 4];   // 64 rows x 16 floats

    int rb = (blockIdx.x >> 2) * K3R;
    int d  = ((blockIdx.x & 3) << 8) + threadIdx.x;

    // cooperative state stage: 1024 floats = 256 float4, one per thread
    sstate[threadIdx.x] =
        reinterpret_cast<const float4*>(g_states + (size_t)rb * STATE_)[threadIdx.x];

    // W_C column-row d: 16 floats as 8 packed ull
    ull wv[8];
    {
        const ulonglong2* wp = reinterpret_cast<const ulonglong2*>(W_C + (size_t)d * STATE_);
        ulonglong2 t0 = wp[0], t1 = wp[1], t2 = wp[2], t3 = wp[3];
        wv[0] = t0.x; wv[1] = t0.y; wv[2] = t1.x; wv[3] = t1.y;
        wv[4] = t2.x; wv[5] = t2.y; wv[6] = t3.x; wv[7] = t3.y;
    }
    float dD = D[d];
    __syncthreads();

    const ull* sbase = reinterpret_cast<const ull*>(sstate);

    // x pipeline: 4 rows in flight
    float xb[4];
    #pragma unroll
    for (int j = 0; j < 4; j++)
        xb[j] = x[(size_t)(rb + j) * DIM_ + d];

    for (int r0 = 0; r0 < K3R; r0 += 4) {
        float xc[4];
        #pragma unroll
        for (int j = 0; j < 4; j++) xc[j] = xb[j];
        if (r0 + 4 < K3R) {
            #pragma unroll
            for (int j = 0; j < 4; j++)
                xb[j] = x[(size_t)(rb + r0 + 4 + j) * DIM_ + d];
        }

        #pragma unroll
        for (int j = 0; j < 4; j++) {
            const ull* sp = sbase + (size_t)(r0 + j) * 8;   // broadcast reads
            ull acc = 0ull;
            #pragma unroll
            for (int k = 0; k < 8; k++) ffma2u(acc, wv[k], sp[k]);
            float2 f = u2f(acc);
            out[(size_t)(rb + r0 + j) * DIM_ + d] = fmaf(dD, xc[j], f.x + f.y);
        }
    }

    // new_state = states[:, L-1, :]
    if (write_tail && blockIdx.x == 0 && threadIdx.x < B_ * STATE_) {
        int bb = threadIdx.x >> 4, ii = threadIdx.x & 15;
        out[(size_t)B_ * L_ * DIM_ + threadIdx.x] =
            g_states[((size_t)bb * L_ + (L_ - 1)) * STATE_ + ii];
    }
}

// =================================================================
extern "C" void kernel_launch(void* const* d_in, const int* in_sizes, int n_in,
                              void* d_out, int out_size) {
    const float* x     = (const float*)d_in[0];
    const float* state = (const float*)d_in[1];
    const float* A     = (const float*)d_in[2];
    const float* W_B   = (const float*)d_in[3];
    const float* W_C   = (const float*)d_in[4];
    const float* D     = (const float*)d_in[5];
    const float* dt_w  = (const float*)d_in[6];
    const float* dt_b  = (const float*)d_in[7];
    const float* ln_w  = (const float*)d_in[8];
    const float* ln_b  = (const float*)d_in[9];
    float* out = (float*)d_out;

    k1_proj<<<(B_ * L_ / 2 * 32) / 256, 256>>>(x, W_B, dt_w, dt_b);      // 1024 blocks
    k2_scan<<<(B_ * NC_) / 2, 32>>>(A, state, ln_w, ln_b);               // 256 blocks
    int tail = (out_size >= B_ * L_ * DIM_ + B_ * STATE_) ? 1 : 0;
    k3_out<<<(B_ * L_ / K3R) * 4, 256>>>(x, W_C, D, out, tail);          // 1024 blocks
}

// round 8
// speedup vs baseline: 1.0988x; 1.0958x over previous
#include <cuda_runtime.h>
#include <math.h>

#define B_      4
#define L_      4096
#define DIM_    1024
#define STATE_  16
#define NC_     128             // chunks per batch
#define CHUNK_  (L_ / NC_)      // 32
#define WARM_   192             // warm-up steps

typedef unsigned long long ull;

// ---------------- scratch (no allocations allowed) ----------------
__device__ float g_dt[B_ * L_];                 // dt[b][t]
__device__ float g_bx[B_ * L_ * STATE_];        // Bx[b][t][i]
__device__ float g_states[B_ * L_ * STATE_];    // normalized states s[b][t][i]

// packed f32x2 FMA on RESIDENT 64-bit regs: c += a * b (lanewise), ZERO movs
__device__ __forceinline__ void ffma2u(ull& c, ull a, ull b) {
    asm("fma.rn.f32x2 %0, %1, %2, %0;" : "+l"(c) : "l"(a), "l"(b));
}
__device__ __forceinline__ float2 u2f(ull u) {
    float2 f;
    asm("mov.b64 {%0, %1}, %2;" : "=f"(f.x), "=f"(f.y) : "l"(u));
    return f;
}

// =================================================================
// K1: per-row projections, TWO rows per warp (W_B stream shared).
//   Bx[i] = sum_d x[d]*W_B[i][d]; dt = clip(softplus(x.dt_w + dt_b))
// Register-lean version: per W-row immediate butterfly reduce, result
// parked in lane i (no acc arrays). 2 blocks/SM guaranteed.
// =================================================================
__global__ void __launch_bounds__(256, 2) k1_proj(const float* __restrict__ x,
                                                  const float* __restrict__ W_B,
                                                  const float* __restrict__ dt_w,
                                                  const float* __restrict__ dt_b) {
    const unsigned FULL = 0xffffffffu;
    int warp = (blockIdx.x * blockDim.x + threadIdx.x) >> 5;
    int lane = threadIdx.x & 31;
    int r0 = warp * 2;
    if (r0 >= B_ * L_) return;

    float dtb = dt_b[0];

    // resident x for the warp's two rows: 32 floats/lane/row as 8 ulonglong2
    const ulonglong2* xr0 = reinterpret_cast<const ulonglong2*>(x + (size_t)r0 * DIM_) + lane;
    const ulonglong2* xr1 = reinterpret_cast<const ulonglong2*>(x + (size_t)(r0 + 1) * DIM_) + lane;
    ulonglong2 xv0[8], xv1[8];
    #pragma unroll
    for (int k = 0; k < 8; k++) { xv0[k] = xr0[k * 32]; xv1[k] = xr1[k * 32]; }

    float keep0 = 0.f, keep1 = 0.f;   // lane i holds result for output i

    #pragma unroll
    for (int i = 0; i < 17; i++) {
        const float* wrow = (i < 16) ? (W_B + (size_t)i * DIM_) : dt_w;
        const ulonglong2* wr = reinterpret_cast<const ulonglong2*>(wrow) + lane;

        // 8 independent 16B loads (MLP=8), consumed by 2 acc chains per row
        ulonglong2 wv[8];
        #pragma unroll
        for (int k = 0; k < 8; k++) wv[k] = wr[k * 32];

        ull a0 = 0ull, a1 = 0ull, b0 = 0ull, b1 = 0ull;
        #pragma unroll
        for (int k = 0; k < 8; k++) {
            ffma2u(a0, xv0[k].x, wv[k].x);
            ffma2u(a1, xv0[k].y, wv[k].y);
            ffma2u(b0, xv1[k].x, wv[k].x);
            ffma2u(b1, xv1[k].y, wv[k].y);
        }
        float2 fa0 = u2f(a0), fa1 = u2f(a1);
        float2 fb0 = u2f(b0), fb1 = u2f(b1);
        float s0 = (fa0.x + fa0.y) + (fa1.x + fa1.y);
        float s1 = (fb0.x + fb0.y) + (fb1.x + fb1.y);

        // full-warp butterfly; every lane ends with the total
        #pragma unroll
        for (int m = 16; m >= 1; m >>= 1) {
            s0 += __shfl_xor_sync(FULL, s0, m);
            s1 += __shfl_xor_sync(FULL, s1, m);
        }
        if (lane == i) { keep0 = s0; keep1 = s1; }
    }

    if (lane < 16) {
        g_bx[(size_t)r0 * STATE_ + lane]       = keep0;
        g_bx[(size_t)(r0 + 1) * STATE_ + lane] = keep1;
    } else if (lane == 16) {
        float z0  = keep0 + dtb;
        float sp0 = (z0 > 15.f) ? z0 : log1pf(expf(z0));
        g_dt[r0] = fminf(fmaxf(sp0, 0.001f), 0.1f);
        float z1  = keep1 + dtb;
        float sp1 = (z1 > 15.f) ? z1 : log1pf(expf(z1));
        g_dt[r0 + 1] = fminf(fmaxf(sp1, 0.001f), 0.1f);
    }
}

// =================================================================
// K2: chunked sequential scan with warm-up, spectral-scale fused in.
// sigma_max <= ||A||_F; ||A||_F <= 0.99 -> scale == 1 exactly.
// (Power-iteration fallback per block for the rare case.)
// =================================================================
__global__ void __launch_bounds__(32) k2_scan(const float* __restrict__ A,
                                              const float* __restrict__ state_in,
                                              const float* __restrict__ ln_w,
                                              const float* __restrict__ ln_b) {
    const unsigned FULL = 0xffffffffu;
    __shared__ float sA[256];
    __shared__ float s_scale;

    int lane = threadIdx.x;
    int seg  = lane >> 4;
    int i    = lane & 15;
    int gidx = blockIdx.x * 2 + seg;  // 0..511
    int b     = gidx & 3;
    int chunk = gidx >> 2;            // same across the warp's two segs
    int cs   = chunk * CHUNK_;
    int ws   = cs - WARM_; if (ws < 0) ws = 0;
    int tend = cs + CHUNK_;

    // ---- fused spectral scale ----
    float ss = 0.f;
    #pragma unroll
    for (int j = 0; j < 8; j++) {
        float a = A[lane * 8 + j];
        sA[lane * 8 + j] = a;
        ss = fmaf(a, a, ss);
    }
    #pragma unroll
    for (int m = 16; m >= 1; m >>= 1) ss += __shfl_xor_sync(FULL, ss, m);
    float scale = 1.0f;
    if (ss > 0.9801f) {               // uniform branch; rarely taken
        __syncwarp();
        if (lane == 0) {
            float v[16];
            #pragma unroll
            for (int k = 0; k < 16; k++) v[k] = 1.0f;
            for (int it = 0; it < 400; ++it) {
                float u[16];
                for (int r = 0; r < 16; r++) {
                    float acc = 0.f;
                    for (int c = 0; c < 16; c++) acc = fmaf(sA[r * 16 + c], v[c], acc);
                    u[r] = acc;
                }
                float w2[16]; float nn = 0.f;
                for (int c = 0; c < 16; c++) {
                    float acc = 0.f;
                    for (int r = 0; r < 16; r++) acc = fmaf(sA[r * 16 + c], u[r], acc);
                    w2[c] = acc; nn += acc * acc;
                }
                float inv = rsqrtf(fmaxf(nn, 1e-30f));
                for (int c = 0; c < 16; c++) v[c] = w2[c] * inv;
            }
            float sig2 = 0.f;
            for (int r = 0; r < 16; r++) {
                float acc = 0.f;
                for (int c = 0; c < 16; c++) acc = fmaf(sA[r * 16 + c], v[c], acc);
                sig2 += acc * acc;
            }
            float sigma = sqrtf(sig2);
            s_scale = (sigma > 0.99f) ? (0.99f / sigma) : 1.0f;
        }
        __syncwarp();
        scale = s_scale;
    }

    // ---- per-lane constants ----
    float w_[16], b_[16];
    #pragma unroll
    for (int j = 0; j < 16; j += 4) {
        float4 t4 = *reinterpret_cast<const float4*>(ln_w + j);
        w_[j] = t4.x; w_[j + 1] = t4.y; w_[j + 2] = t4.z; w_[j + 3] = t4.w;
        float4 u4 = *reinterpret_cast<const float4*>(ln_b + j);
        b_[j] = u4.x; b_[j + 1] = u4.y; b_[j + 2] = u4.z; b_[j + 3] = u4.w;
    }
    float an[16], ap[16];
    #pragma unroll
    for (int j = 0; j < 16; j += 4) {
        float4 a4 = *reinterpret_cast<const float4*>(A + i * 16 + j);
        an[j] = a4.x * scale; an[j + 1] = a4.y * scale;
        an[j + 2] = a4.z * scale; an[j + 3] = a4.w * scale;
    }
    float aw1 = 0.f, ab = 0.f;
    #pragma unroll
    for (int j = 0; j < 16; j++) {
        ap[j] = an[j] * w_[j];
        aw1  += ap[j];
        ab    = fmaf(an[j], b_[j], ab);
    }
    float wi = ln_w[i];
    float bi = ln_b[i];

    const float* dtp = g_dt + (size_t)b * L_;
    const float* bxp = g_bx + (size_t)b * L_ * STATE_ + i;
    float*       stp = g_states + (size_t)b * L_ * STATE_ + i;

    // prologue: h_ws = s0 + dt[ws]*(An s0) + bx[ws]
    float s0 = (ws == 0) ? state_in[b * STATE_ + i] : 0.f;
    float p0 = 0.f, p1 = 0.f, p2 = 0.f, p3 = 0.f;
    #pragma unroll
    for (int j = 0; j < 16; j += 4) {
        p0 = fmaf(an[j],     __shfl_sync(FULL, s0, j,     16), p0);
        p1 = fmaf(an[j + 1], __shfl_sync(FULL, s0, j + 1, 16), p1);
        p2 = fmaf(an[j + 2], __shfl_sync(FULL, s0, j + 2, 16), p2);
        p3 = fmaf(an[j + 3], __shfl_sync(FULL, s0, j + 3, 16), p3);
    }
    float g0 = (p0 + p1) + (p2 + p3);
    float h = fmaf(dtp[ws], g0, s0) + bxp[(size_t)ws * STATE_];

    int tp1 = ws + 1; if (tp1 > L_ - 1) tp1 = L_ - 1;
    int tp2 = ws + 2; if (tp2 > L_ - 1) tp2 = L_ - 1;
    int tp3 = ws + 3; if (tp3 > L_ - 1) tp3 = L_ - 1;
    float dtA = dtp[tp1], bxA = bxp[(size_t)tp1 * STATE_];
    float dtB = dtp[tp2], bxB = bxp[(size_t)tp2 * STATE_];
    float dtC = dtp[tp3], bxC = bxp[(size_t)tp3 * STATE_];

    for (int t = ws; t < tend; ++t) {
        float hv[16];
        #pragma unroll
        for (int j = 0; j < 16; j++) hv[j] = __shfl_sync(FULL, h, j, 16);

        float m0, m1, m2, m3, u0, u1, q0, q1, q2, q3;
        m0 = ap[0] * hv[0]; m1 = ap[1] * hv[1]; m2 = ap[2] * hv[2]; m3 = ap[3] * hv[3];
        u0 = hv[0] + hv[1]; u1 = hv[2] + hv[3];
        q0 = hv[0] * hv[0]; q1 = hv[1] * hv[1]; q2 = hv[2] * hv[2]; q3 = hv[3] * hv[3];
        #pragma unroll
        for (int j = 4; j < 16; j += 4) {
            m0 = fmaf(ap[j],     hv[j],     m0);
            m1 = fmaf(ap[j + 1], hv[j + 1], m1);
            m2 = fmaf(ap[j + 2], hv[j + 2], m2);
            m3 = fmaf(ap[j + 3], hv[j + 3], m3);
            u0 += hv[j] + hv[j + 1];
            u1 += hv[j + 2] + hv[j + 3];
            q0 = fmaf(hv[j],     hv[j],     q0);
            q1 = fmaf(hv[j + 1], hv[j + 1], q1);
            q2 = fmaf(hv[j + 2], hv[j + 2], q2);
            q3 = fmaf(hv[j + 3], hv[j + 3], q3);
        }
        float g = (m0 + m1) + (m2 + m3);
        float u = u0 + u1;
        float q = (q0 + q1) + (q2 + q3);

        float mu    = u * 0.0625f;
        float var   = fmaf(-mu, mu, q * 0.0625f);
        float alpha = rsqrtf(var + 1e-5f);
        float hm    = h - mu;

        if (t >= cs) stp[(size_t)t * STATE_] = fmaf(alpha * hm, wi, bi);

        float dtn = dtA, bxn = bxA;
        dtA = dtB; bxA = bxB;
        dtB = dtC; bxB = bxC;
        int tn = t + 4; if (tn > L_ - 1) tn = L_ - 1;
        dtC = dtp[tn]; bxC = bxp[(size_t)tn * STATE_];

        float t1 = fmaf(-mu, aw1, g);
        float t2 = fmaf(dtn, t1, hm * wi);
        h = fmaf(alpha, t2, fmaf(dtn, ab, bi) + bxn);
    }
}

// =================================================================
// K3: y = states @ W_C^T + D*x.  Occupancy-first tiling:
//   one output column d per thread (W_C[d][:] = 8 resident ull regs),
//   64 rows per block staged through 4KB smem (broadcast LDS.64),
//   x loads scalar-coalesced with MLP=4, 1024 blocks, low regs.
// =================================================================
#define K3R 64

__global__ void __launch_bounds__(256) k3_out(const float* __restrict__ x,
                                              const float* __restrict__ W_C,
                                              const float* __restrict__ D,
                                              float* __restrict__ out,
                                              int write_tail) {
    __shared__ float4 sstate[K3R * 4];   // 64 rows x 16 floats

    int rb = (blockIdx.x >> 2) * K3R;
    int d  = ((blockIdx.x & 3) << 8) + threadIdx.x;

    // cooperative state stage: 1024 floats = 256 float4, one per thread
    sstate[threadIdx.x] =
        reinterpret_cast<const float4*>(g_states + (size_t)rb * STATE_)[threadIdx.x];

    // W_C column-row d: 16 floats as 8 packed ull
    ull wv[8];
    {
        const ulonglong2* wp = reinterpret_cast<const ulonglong2*>(W_C + (size_t)d * STATE_);
        ulonglong2 t0 = wp[0], t1 = wp[1], t2 = wp[2], t3 = wp[3];
        wv[0] = t0.x; wv[1] = t0.y; wv[2] = t1.x; wv[3] = t1.y;
        wv[4] = t2.x; wv[5] = t2.y; wv[6] = t3.x; wv[7] = t3.y;
    }
    float dD = D[d];
    __syncthreads();

    const ull* sbase = reinterpret_cast<const ull*>(sstate);

    // x pipeline: 4 rows in flight
    float xb[4];
    #pragma unroll
    for (int j = 0; j < 4; j++)
        xb[j] = x[(size_t)(rb + j) * DIM_ + d];

    for (int r0 = 0; r0 < K3R; r0 += 4) {
        float xc[4];
        #pragma unroll
        for (int j = 0; j < 4; j++) xc[j] = xb[j];
        if (r0 + 4 < K3R) {
            #pragma unroll
            for (int j = 0; j < 4; j++)
                xb[j] = x[(size_t)(rb + r0 + 4 + j) * DIM_ + d];
        }

        #pragma unroll
        for (int j = 0; j < 4; j++) {
            const ull* sp = sbase + (size_t)(r0 + j) * 8;   // broadcast reads
            ull acc = 0ull;
            #pragma unroll
            for (int k = 0; k < 8; k++) ffma2u(acc, wv[k], sp[k]);
            float2 f = u2f(acc);
            out[(size_t)(rb + r0 + j) * DIM_ + d] = fmaf(dD, xc[j], f.x + f.y);
        }
    }

    // new_state = states[:, L-1, :]
    if (write_tail && blockIdx.x == 0 && threadIdx.x < B_ * STATE_) {
        int bb = threadIdx.x >> 4, ii = threadIdx.x & 15;
        out[(size_t)B_ * L_ * DIM_ + threadIdx.x] =
            g_states[((size_t)bb * L_ + (L_ - 1)) * STATE_ + ii];
    }
}

// =================================================================
extern "C" void kernel_launch(void* const* d_in, const int* in_sizes, int n_in,
                              void* d_out, int out_size) {
    const float* x     = (const float*)d_in[0];
    const float* state = (const float*)d_in[1];
    const float* A     = (const float*)d_in[2];
    const float* W_B   = (const float*)d_in[3];
    const float* W_C   = (const float*)d_in[4];
    const float* D     = (const float*)d_in[5];
    const float* dt_w  = (const float*)d_in[6];
    const float* dt_b  = (const float*)d_in[7];
    const float* ln_w  = (const float*)d_in[8];
    const float* ln_b  = (const float*)d_in[9];
    float* out = (float*)d_out;

    k1_proj<<<(B_ * L_ / 2 * 32) / 256, 256>>>(x, W_B, dt_w, dt_b);      // 1024 blocks
    k2_scan<<<(B_ * NC_) / 2, 32>>>(A, state, ln_w, ln_b);               // 256 blocks
    int tail = (out_size >= B_ * L_ * DIM_ + B_ * STATE_) ? 1 : 0;
    k3_out<<<(B_ * L_ / K3R) * 4, 256>>>(x, W_C, D, out, tail);          // 1024 blocks
}

// round 9
// speedup vs baseline: 1.2374x; 1.1261x over previous
#include <cuda_runtime.h>
#include <math.h>

#define B_      4
#define L_      4096
#define DIM_    1024
#define STATE_  16
#define NC_     128             // chunks per batch
#define CHUNK_  (L_ / NC_)      // 32
#define WARM_   192             // warm-up steps

typedef unsigned long long ull;

// ---------------- scratch (no allocations allowed) ----------------
__device__ float g_dt[B_ * L_];                 // dt[b][t]
__device__ float g_bx[B_ * L_ * STATE_];        // Bx[b][t][i]
__device__ float g_states[B_ * L_ * STATE_];    // normalized states s[b][t][i]

// packed f32x2 FMA on RESIDENT 64-bit regs: c += a * b (lanewise), ZERO movs
__device__ __forceinline__ void ffma2u(ull& c, ull a, ull b) {
    asm("fma.rn.f32x2 %0, %1, %2, %0;" : "+l"(c) : "l"(a), "l"(b));
}
__device__ __forceinline__ float2 u2f(ull u) {
    float2 f;
    asm("mov.b64 {%0, %1}, %2;" : "=f"(f.x), "=f"(f.y) : "l"(u));
    return f;
}

// =================================================================
// K1: projections with split-K.  A warp-pair shares a row-pair:
// warp half 0 covers d[0,512), half 1 covers d[512,1024).
// xv = 32 regs/lane -> ~65 regs total -> 4 blocks/SM (32 warps).
// Halves combined through smem.
// =================================================================
__global__ void __launch_bounds__(256, 4) k1_proj(const float* __restrict__ x,
                                                  const float* __restrict__ W_B,
                                                  const float* __restrict__ dt_w,
                                                  const float* __restrict__ dt_b) {
    const unsigned FULL = 0xffffffffu;
    __shared__ float s_part[4][2][2][17];   // [pair][half][row][output]

    int w    = threadIdx.x >> 5;            // warp in block 0..7
    int lane = threadIdx.x & 31;
    int pib  = w >> 1;                      // pair in block 0..3
    int half = w & 1;
    int pair = blockIdx.x * 4 + pib;        // 0..8191
    int r0 = pair * 2;
    int off = half * 512;

    // resident x halves for the two rows: 16 floats/lane/row
    const ulonglong2* xr0 =
        reinterpret_cast<const ulonglong2*>(x + (size_t)r0 * DIM_ + off) + lane;
    const ulonglong2* xr1 =
        reinterpret_cast<const ulonglong2*>(x + (size_t)(r0 + 1) * DIM_ + off) + lane;
    ulonglong2 xv0[4], xv1[4];
    #pragma unroll
    for (int k = 0; k < 4; k++) { xv0[k] = xr0[k * 32]; xv1[k] = xr1[k * 32]; }

    float keep0 = 0.f, keep1 = 0.f;   // lane i holds partial for output i

    #pragma unroll
    for (int i = 0; i < 17; i++) {
        const float* wrow = (i < 16) ? (W_B + (size_t)i * DIM_) : dt_w;
        const ulonglong2* wr = reinterpret_cast<const ulonglong2*>(wrow + off) + lane;

        ulonglong2 wv[4];
        #pragma unroll
        for (int k = 0; k < 4; k++) wv[k] = wr[k * 32];

        ull a0 = 0ull, a1 = 0ull, b0 = 0ull, b1 = 0ull;
        #pragma unroll
        for (int k = 0; k < 4; k++) {
            ffma2u(a0, xv0[k].x, wv[k].x);
            ffma2u(a1, xv0[k].y, wv[k].y);
            ffma2u(b0, xv1[k].x, wv[k].x);
            ffma2u(b1, xv1[k].y, wv[k].y);
        }
        float2 fa0 = u2f(a0), fa1 = u2f(a1);
        float2 fb0 = u2f(b0), fb1 = u2f(b1);
        float s0 = (fa0.x + fa0.y) + (fa1.x + fa1.y);
        float s1 = (fb0.x + fb0.y) + (fb1.x + fb1.y);

        #pragma unroll
        for (int m = 16; m >= 1; m >>= 1) {
            s0 += __shfl_xor_sync(FULL, s0, m);
            s1 += __shfl_xor_sync(FULL, s1, m);
        }
        if (lane == i) { keep0 = s0; keep1 = s1; }
    }

    if (lane < 17) {
        s_part[pib][half][0][lane] = keep0;
        s_part[pib][half][1][lane] = keep1;
    }
    __syncthreads();

    if (half == 0 && lane < 17) {
        float v0 = s_part[pib][0][0][lane] + s_part[pib][1][0][lane];
        float v1 = s_part[pib][0][1][lane] + s_part[pib][1][1][lane];
        if (lane < 16) {
            g_bx[(size_t)r0 * STATE_ + lane]       = v0;
            g_bx[(size_t)(r0 + 1) * STATE_ + lane] = v1;
        } else {
            float dtb = dt_b[0];
            float z0  = v0 + dtb;
            float sp0 = (z0 > 15.f) ? z0 : log1pf(expf(z0));
            g_dt[r0] = fminf(fmaxf(sp0, 0.001f), 0.1f);
            float z1  = v1 + dtb;
            float sp1 = (z1 > 15.f) ? z1 : log1pf(expf(z1));
            g_dt[r0 + 1] = fminf(fmaxf(sp1, 0.001f), 0.1f);
        }
    }
}

// =================================================================
// K2: chunked scan, TWO interleaved chunk-streams per 16-lane group
// (software hyperthreading: stream B issues while stream A's shfl /
// rsqrt latency drains). Spectral-scale check fused (||A||_F bound).
// Group g handles jobs g (stream A) and g+256 (stream B); job = (b,chunk).
// Uniform 224-iteration loop; chunk-0 streams idle after 32 steps
// (stores predicated on cs <= t < tend; loads index-clamped).
// =================================================================
__global__ void __launch_bounds__(32) k2_scan(const float* __restrict__ A,
                                              const float* __restrict__ state_in,
                                              const float* __restrict__ ln_w,
                                              const float* __restrict__ ln_b) {
    const unsigned FULL = 0xffffffffu;
    __shared__ float sA[256];
    __shared__ float s_scale;

    int lane = threadIdx.x;
    int seg  = lane >> 4;
    int i    = lane & 15;

    int gA = blockIdx.x * 2 + seg;        // 0..255
    int gB = gA + 256;                    // 256..511
    int bA = gA & 3,  chA = gA >> 2;      // chunk 0..63
    int bB = gB & 3,  chB = gB >> 2;      // chunk 64..127
    int csA = chA * CHUNK_, csB = chB * CHUNK_;
    int wsA = csA - WARM_; if (wsA < 0) wsA = 0;
    int wsB = csB - WARM_;                // always > 0 for chB >= 64
    int teA = csA + CHUNK_, teB = csB + CHUNK_;

    // ---- fused spectral scale (Frobenius fast path) ----
    float ss = 0.f;
    #pragma unroll
    for (int j = 0; j < 8; j++) {
        float a = A[lane * 8 + j];
        sA[lane * 8 + j] = a;
        ss = fmaf(a, a, ss);
    }
    #pragma unroll
    for (int m = 16; m >= 1; m >>= 1) ss += __shfl_xor_sync(FULL, ss, m);
    float scale = 1.0f;
    if (ss > 0.9801f) {               // uniform branch; rarely taken
        __syncwarp();
        if (lane == 0) {
            float v[16];
            #pragma unroll
            for (int k = 0; k < 16; k++) v[k] = 1.0f;
            for (int it = 0; it < 400; ++it) {
                float u[16];
                for (int r = 0; r < 16; r++) {
                    float acc = 0.f;
                    for (int c = 0; c < 16; c++) acc = fmaf(sA[r * 16 + c], v[c], acc);
                    u[r] = acc;
                }
                float w2[16]; float nn = 0.f;
                for (int c = 0; c < 16; c++) {
                    float acc = 0.f;
                    for (int r = 0; r < 16; r++) acc = fmaf(sA[r * 16 + c], u[r], acc);
                    w2[c] = acc; nn += acc * acc;
                }
                float inv = rsqrtf(fmaxf(nn, 1e-30f));
                for (int c = 0; c < 16; c++) v[c] = w2[c] * inv;
            }
            float sig2 = 0.f;
            for (int r = 0; r < 16; r++) {
                float acc = 0.f;
                for (int c = 0; c < 16; c++) acc = fmaf(sA[r * 16 + c], v[c], acc);
                sig2 += acc * acc;
            }
            float sigma = sqrtf(sig2);
            s_scale = (sigma > 0.99f) ? (0.99f / sigma) : 1.0f;
        }
        __syncwarp();
        scale = s_scale;
    }

    // ---- per-lane constants (shared by both streams) ----
    float w_[16], b_[16];
    #pragma unroll
    for (int j = 0; j < 16; j += 4) {
        float4 t4 = *reinterpret_cast<const float4*>(ln_w + j);
        w_[j] = t4.x; w_[j + 1] = t4.y; w_[j + 2] = t4.z; w_[j + 3] = t4.w;
        float4 u4 = *reinterpret_cast<const float4*>(ln_b + j);
        b_[j] = u4.x; b_[j + 1] = u4.y; b_[j + 2] = u4.z; b_[j + 3] = u4.w;
    }
    float an[16], ap[16];
    #pragma unroll
    for (int j = 0; j < 16; j += 4) {
        float4 a4 = *reinterpret_cast<const float4*>(A + i * 16 + j);
        an[j] = a4.x * scale; an[j + 1] = a4.y * scale;
        an[j + 2] = a4.z * scale; an[j + 3] = a4.w * scale;
    }
    float aw1 = 0.f, ab = 0.f;
    #pragma unroll
    for (int j = 0; j < 16; j++) {
        ap[j] = an[j] * w_[j];
        aw1  += ap[j];
        ab    = fmaf(an[j], b_[j], ab);
    }
    float wi = ln_w[i];
    float bi = ln_b[i];

    const float* dtpA = g_dt + (size_t)bA * L_;
    const float* bxpA = g_bx + (size_t)bA * L_ * STATE_ + i;
    float*       stpA = g_states + (size_t)bA * L_ * STATE_ + i;
    const float* dtpB = g_dt + (size_t)bB * L_;
    const float* bxpB = g_bx + (size_t)bB * L_ * STATE_ + i;
    float*       stpB = g_states + (size_t)bB * L_ * STATE_ + i;

    // prologue for each stream: h = s0 + dt[ws]*(An s0) + bx[ws]
    float s0A = (wsA == 0) ? state_in[bA * STATE_ + i] : 0.f;
    float pA0 = 0.f, pA1 = 0.f, pA2 = 0.f, pA3 = 0.f;
    #pragma unroll
    for (int j = 0; j < 16; j += 4) {
        pA0 = fmaf(an[j],     __shfl_sync(FULL, s0A, j,     16), pA0);
        pA1 = fmaf(an[j + 1], __shfl_sync(FULL, s0A, j + 1, 16), pA1);
        pA2 = fmaf(an[j + 2], __shfl_sync(FULL, s0A, j + 2, 16), pA2);
        pA3 = fmaf(an[j + 3], __shfl_sync(FULL, s0A, j + 3, 16), pA3);
    }
    float hA = fmaf(dtpA[wsA], (pA0 + pA1) + (pA2 + pA3), s0A) + bxpA[(size_t)wsA * STATE_];
    float hB = bxpB[(size_t)wsB * STATE_];   // s0B == 0 always (chB >= 64)

    // prefetch queues, depth 3 per stream
    float dtA1 = dtpA[wsA + 1 > L_ - 1 ? L_ - 1 : wsA + 1];
    float dtA2 = dtpA[wsA + 2 > L_ - 1 ? L_ - 1 : wsA + 2];
    float dtA3 = dtpA[wsA + 3 > L_ - 1 ? L_ - 1 : wsA + 3];
    float bxA1 = bxpA[(size_t)(wsA + 1 > L_ - 1 ? L_ - 1 : wsA + 1) * STATE_];
    float bxA2 = bxpA[(size_t)(wsA + 2 > L_ - 1 ? L_ - 1 : wsA + 2) * STATE_];
    float bxA3 = bxpA[(size_t)(wsA + 3 > L_ - 1 ? L_ - 1 : wsA + 3) * STATE_];
    float dtB1 = dtpB[wsB + 1], dtB2 = dtpB[wsB + 2], dtB3 = dtpB[wsB + 3];
    float bxB1 = bxpB[(size_t)(wsB + 1) * STATE_];
    float bxB2 = bxpB[(size_t)(wsB + 2) * STATE_];
    float bxB3 = bxpB[(size_t)(wsB + 3) * STATE_];

    #pragma unroll 2
    for (int k = 0; k < WARM_ + CHUNK_; ++k) {
        int tA = wsA + k;
        int tB = wsB + k;

        // ---- broadcast both states (32 independent shfls) ----
        float hvA[16], hvB[16];
        #pragma unroll
        for (int j = 0; j < 16; j++) {
            hvA[j] = __shfl_sync(FULL, hA, j, 16);
            hvB[j] = __shfl_sync(FULL, hB, j, 16);
        }

        // ---- stream A trees ----
        float mA0, mA1, mA2, mA3, uA0, uA1, qA0, qA1, qA2, qA3;
        mA0 = ap[0] * hvA[0]; mA1 = ap[1] * hvA[1]; mA2 = ap[2] * hvA[2]; mA3 = ap[3] * hvA[3];
        uA0 = hvA[0] + hvA[1]; uA1 = hvA[2] + hvA[3];
        qA0 = hvA[0] * hvA[0]; qA1 = hvA[1] * hvA[1]; qA2 = hvA[2] * hvA[2]; qA3 = hvA[3] * hvA[3];
        // ---- stream B trees ----
        float mB0, mB1, mB2, mB3, uB0, uB1, qB0, qB1, qB2, qB3;
        mB0 = ap[0] * hvB[0]; mB1 = ap[1] * hvB[1]; mB2 = ap[2] * hvB[2]; mB3 = ap[3] * hvB[3];
        uB0 = hvB[0] + hvB[1]; uB1 = hvB[2] + hvB[3];
        qB0 = hvB[0] * hvB[0]; qB1 = hvB[1] * hvB[1]; qB2 = hvB[2] * hvB[2]; qB3 = hvB[3] * hvB[3];
        #pragma unroll
        for (int j = 4; j < 16; j += 4) {
            mA0 = fmaf(ap[j],     hvA[j],     mA0);
            mA1 = fmaf(ap[j + 1], hvA[j + 1], mA1);
            mA2 = fmaf(ap[j + 2], hvA[j + 2], mA2);
            mA3 = fmaf(ap[j + 3], hvA[j + 3], mA3);
            uA0 += hvA[j] + hvA[j + 1];
            uA1 += hvA[j + 2] + hvA[j + 3];
            qA0 = fmaf(hvA[j],     hvA[j],     qA0);
            qA1 = fmaf(hvA[j + 1], hvA[j + 1], qA1);
            qA2 = fmaf(hvA[j + 2], hvA[j + 2], qA2);
            qA3 = fmaf(hvA[j + 3], hvA[j + 3], qA3);
            mB0 = fmaf(ap[j],     hvB[j],     mB0);
            mB1 = fmaf(ap[j + 1], hvB[j + 1], mB1);
            mB2 = fmaf(ap[j + 2], hvB[j + 2], mB2);
            mB3 = fmaf(ap[j + 3], hvB[j + 3], mB3);
            uB0 += hvB[j] + hvB[j + 1];
            uB1 += hvB[j + 2] + hvB[j + 3];
            qB0 = fmaf(hvB[j],     hvB[j],     qB0);
            qB1 = fmaf(hvB[j + 1], hvB[j + 1], qB1);
            qB2 = fmaf(hvB[j + 2], hvB[j + 2], qB2);
            qB3 = fmaf(hvB[j + 3], hvB[j + 3], qB3);
        }
        float gA = (mA0 + mA1) + (mA2 + mA3);
        float uA = uA0 + uA1;
        float qA = (qA0 + qA1) + (qA2 + qA3);
        float gB = (mB0 + mB1) + (mB2 + mB3);
        float uB = uB0 + uB1;
        float qB = (qB0 + qB1) + (qB2 + qB3);

        float muA    = uA * 0.0625f;
        float varA   = fmaf(-muA, muA, qA * 0.0625f);
        float alphaA = rsqrtf(varA + 1e-5f);
        float hmA    = hA - muA;
        float muB    = uB * 0.0625f;
        float varB   = fmaf(-muB, muB, qB * 0.0625f);
        float alphaB = rsqrtf(varB + 1e-5f);
        float hmB    = hB - muB;

        if (tA >= csA && tA < teA) stpA[(size_t)tA * STATE_] = fmaf(alphaA * hmA, wi, bi);
        if (tB >= csB)             stpB[(size_t)tB * STATE_] = fmaf(alphaB * hmB, wi, bi);

        // rotate prefetch queues
        float dtnA = dtA1, bxnA = bxA1;
        dtA1 = dtA2; bxA1 = bxA2; dtA2 = dtA3; bxA2 = bxA3;
        int tnA = tA + 4; if (tnA > L_ - 1) tnA = L_ - 1;
        dtA3 = dtpA[tnA]; bxA3 = bxpA[(size_t)tnA * STATE_];
        float dtnB = dtB1, bxnB = bxB1;
        dtB1 = dtB2; bxB1 = bxB2; dtB2 = dtB3; bxB2 = bxB3;
        int tnB = tB + 4; if (tnB > L_ - 1) tnB = L_ - 1;
        dtB3 = dtpB[tnB]; bxB3 = bxpB[(size_t)tnB * STATE_];

        float t1A = fmaf(-muA, aw1, gA);
        float t2A = fmaf(dtnA, t1A, hmA * wi);
        hA = fmaf(alphaA, t2A, fmaf(dtnA, ab, bi) + bxnA);
        float t1B = fmaf(-muB, aw1, gB);
        float t2B = fmaf(dtnB, t1B, hmB * wi);
        hB = fmaf(alphaB, t2B, fmaf(dtnB, ab, bi) + bxnB);
    }
}

// =================================================================
// K3: y = states @ W_C^T + D*x.  2 cols/thread (block covers 512
// cols x 64 rows), states staged in 4KB smem, FFMA2:LDS = 2:1,
// ~70 regs -> 3 blocks/SM, x prefetch depth 4.
// =================================================================
#define K3R 64

__global__ void __launch_bounds__(256) k3_out(const float* __restrict__ x,
                                              const float* __restrict__ W_C,
                                              const float* __restrict__ D,
                                              float* __restrict__ out,
                                              int write_tail) {
    __shared__ float4 sstate[K3R * 4];   // 64 rows x 16 floats

    int rb = (blockIdx.x >> 1) * K3R;
    int d  = ((blockIdx.x & 1) << 9) + threadIdx.x * 2;   // 2 consecutive cols

    // cooperative state stage: 1024 floats = 256 float4
    sstate[threadIdx.x] =
        reinterpret_cast<const float4*>(g_states + (size_t)rb * STATE_)[threadIdx.x];

    // W_C rows d and d+1: 16 floats each as 8 packed ull
    ull wa[8], wb[8];
    {
        const ulonglong2* wp = reinterpret_cast<const ulonglong2*>(W_C + (size_t)d * STATE_);
        #pragma unroll
        for (int k = 0; k < 4; k++) { ulonglong2 t = wp[k];     wa[2*k] = t.x; wa[2*k+1] = t.y; }
        #pragma unroll
        for (int k = 0; k < 4; k++) { ulonglong2 t = wp[4 + k]; wb[2*k] = t.x; wb[2*k+1] = t.y; }
    }
    float2 dd = *reinterpret_cast<const float2*>(D + d);
    __syncthreads();

    const ull* sbase = reinterpret_cast<const ull*>(sstate);

    // x pipeline: 4 rows in flight (float2 loads, coalesced)
    float2 xb[4];
    #pragma unroll
    for (int j = 0; j < 4; j++)
        xb[j] = *reinterpret_cast<const float2*>(x + (size_t)(rb + j) * DIM_ + d);

    for (int r0 = 0; r0 < K3R; r0 += 4) {
        float2 xc[4];
        #pragma unroll
        for (int j = 0; j < 4; j++) xc[j] = xb[j];
        if (r0 + 4 < K3R) {
            #pragma unroll
            for (int j = 0; j < 4; j++)
                xb[j] = *reinterpret_cast<const float2*>(x + (size_t)(rb + r0 + 4 + j) * DIM_ + d);
        }

        #pragma unroll
        for (int j = 0; j < 4; j++) {
            const ull* sp = sbase + (size_t)(r0 + j) * 8;   // broadcast LDS.64
            ull sv[8];
            #pragma unroll
            for (int k = 0; k < 8; k++) sv[k] = sp[k];
            ull accA = 0ull, accB = 0ull;
            #pragma unroll
            for (int k = 0; k < 8; k++) {
                ffma2u(accA, wa[k], sv[k]);
                ffma2u(accB, wb[k], sv[k]);
            }
            float2 fa = u2f(accA), fb = u2f(accB);
            float2 y;
            y.x = fmaf(dd.x, xc[j].x, fa.x + fa.y);
            y.y = fmaf(dd.y, xc[j].y, fb.x + fb.y);
            *reinterpret_cast<float2*>(out + (size_t)(rb + r0 + j) * DIM_ + d) = y;
        }
    }

    // new_state = states[:, L-1, :]
    if (write_tail && blockIdx.x == 0 && threadIdx.x < B_ * STATE_) {
        int bb = threadIdx.x >> 4, ii = threadIdx.x & 15;
        out[(size_t)B_ * L_ * DIM_ + threadIdx.x] =
            g_states[((size_t)bb * L_ + (L_ - 1)) * STATE_ + ii];
    }
}

// =================================================================
extern "C" void kernel_launch(void* const* d_in, const int* in_sizes, int n_in,
                              void* d_out, int out_size) {
    const float* x     = (const float*)d_in[0];
    const float* state = (const float*)d_in[1];
    const float* A     = (const float*)d_in[2];
    const float* W_B   = (const float*)d_in[3];
    const float* W_C   = (const float*)d_in[4];
    const float* D     = (const float*)d_in[5];
    const float* dt_w  = (const float*)d_in[6];
    const float* dt_b  = (const float*)d_in[7];
    const float* ln_w  = (const float*)d_in[8];
    const float* ln_b  = (const float*)d_in[9];
    float* out = (float*)d_out;

    k1_proj<<<B_ * L_ / 8, 256>>>(x, W_B, dt_w, dt_b);                   // 2048 blocks
    k2_scan<<<128, 32>>>(A, state, ln_w, ln_b);                          // 128 blocks, 2 streams/group
    int tail = (out_size >= B_ * L_ * DIM_ + B_ * STATE_) ? 1 : 0;
    k3_out<<<(B_ * L_ / K3R) * 2, 256>>>(x, W_C, D, out, tail);          // 512 blocks
}